// round 3
// baseline (speedup 1.0000x reference)
#include <cuda_runtime.h>
#include <cstdint>
#include <cstddef>

#define N_NODES 100000
#define N_EDGES 1600000

// ---------------- scratch (device globals; no runtime allocation) ----------------
// g_NP layout per node (256 floats):
//   [0:64)    x_n @ W_f[0:64]   + b_f   (src part, f)
//   [64:128)  x_n @ W_s[0:64]   + b_s   (src part, s)
//   [128:192) x_n @ W_f[64:128]         (tgt part, f)
//   [192:256) x_n @ W_s[64:128]         (tgt part, s)
__device__ __align__(16) float g_NP[(size_t)N_NODES * 256];
__device__ __align__(16) float g_msg[(size_t)N_NODES * 64];
__device__ double g_stats[128];   // [0:64) sum, [64:128) sumsq
__device__ float g_scale[64];
__device__ float g_shift[64];
__device__ int   g_is64;

// ---------------- helpers ----------------
union F2U { unsigned long long u; float2 f2; float f[2]; };

__device__ __forceinline__ unsigned long long ffma2(unsigned long long a,
                                                    unsigned long long b,
                                                    unsigned long long c) {
    unsigned long long d;
    asm("fma.rn.f32x2 %0, %1, %2, %3;" : "=l"(d) : "l"(a), "l"(b), "l"(c));
    return d;
}
__device__ __forceinline__ unsigned long long pk2(float x, float y) {
    F2U u; u.f2 = make_float2(x, y); return u.u;
}
__device__ __forceinline__ void red4(float* p, float a, float b, float c, float d) {
    asm volatile("red.global.add.v4.f32 [%0], {%1,%2,%3,%4};"
                 :: "l"(p), "f"(a), "f"(b), "f"(c), "f"(d) : "memory");
}
__device__ __forceinline__ float sigmoidf_(float x) {
    return __fdividef(1.0f, 1.0f + __expf(-x));
}
__device__ __forceinline__ float softplusf_(float x) {
    return (x > 15.0f) ? x : __logf(1.0f + __expf(x));
}

// ---------------- kernel 0: edge_index dtype detection ----------------
__global__ void detect_dtype(const unsigned int* __restrict__ ei32) {
    __shared__ unsigned int acc;
    int tid = threadIdx.x;
    if (tid == 0) acc = 0u;
    __syncthreads();
    unsigned int v = 0u;
    for (int i = tid; i < 1024; i += 256) v |= ei32[2 * i + 1];
    atomicOr(&acc, v);
    __syncthreads();
    if (tid == 0) g_is64 = (acc == 0u) ? 1 : 0;
}

// ---------------- kernel 1: per-node projection GEMM ----------------
__global__ void __launch_bounds__(256, 2) node_gemm(
    const float* __restrict__ node, const float* __restrict__ Wf,
    const float* __restrict__ bf, const float* __restrict__ Ws,
    const float* __restrict__ bs)
{
    __shared__ float Ast[32][68];    // A transposed: [k][node]
    __shared__ float Bs[32][256];

    const int tid = threadIdx.x;
    const int cx = tid & 31;         // cols 8*cx .. 8*cx+7 of 256
    const int ey = tid >> 5;         // nodes 8*ey .. 8*ey+7 of 64
    const int nb = blockIdx.x * 64;

    F2U acc[8][4];
#pragma unroll
    for (int i = 0; i < 8; ++i)
#pragma unroll
        for (int j = 0; j < 4; ++j) acc[i][j].u = 0ULL;

    for (int kt = 0; kt < 2; ++kt) {
#pragma unroll
        for (int it = 0; it < 8; ++it) {
            int idx = it * 256 + tid;
            int n = idx >> 5, k = idx & 31;
            float v = 0.0f;
            if (nb + n < N_NODES) v = node[(size_t)(nb + n) * 64 + kt * 32 + k];
            Ast[k][n] = v;
        }
#pragma unroll
        for (int it = 0; it < 32; ++it) {
            int idx = it * 256 + tid;
            int k = idx >> 8, c = idx & 255;
            int kk = kt * 32 + k;
            float v;
            if (c < 64)       v = Wf[kk * 64 + c];
            else if (c < 128) v = Ws[kk * 64 + (c - 64)];
            else if (c < 192) v = Wf[(64 + kk) * 64 + (c - 128)];
            else              v = Ws[(64 + kk) * 64 + (c - 192)];
            Bs[k][c] = v;
        }
        __syncthreads();
#pragma unroll 8
        for (int k = 0; k < 32; ++k) {
            float4 a0 = *(const float4*)&Ast[k][ey * 8];
            float4 a1 = *(const float4*)&Ast[k][ey * 8 + 4];
            float4 b0 = *(const float4*)&Bs[k][cx * 8];
            float4 b1 = *(const float4*)&Bs[k][cx * 8 + 4];
            unsigned long long bp[4] = { pk2(b0.x, b0.y), pk2(b0.z, b0.w),
                                         pk2(b1.x, b1.y), pk2(b1.z, b1.w) };
            float av[8] = { a0.x, a0.y, a0.z, a0.w, a1.x, a1.y, a1.z, a1.w };
#pragma unroll
            for (int i = 0; i < 8; ++i) {
                unsigned long long aa = pk2(av[i], av[i]);
#pragma unroll
                for (int j = 0; j < 4; ++j) acc[i][j].u = ffma2(aa, bp[j], acc[i][j].u);
            }
        }
        __syncthreads();
    }

    float bias[8];
#pragma unroll
    for (int j = 0; j < 8; ++j) {
        int c = cx * 8 + j;
        bias[j] = (c < 64) ? bf[c] : ((c < 128) ? bs[c - 64] : 0.0f);
    }
#pragma unroll
    for (int i = 0; i < 8; ++i) {
        int n = nb + ey * 8 + i;
        if (n < N_NODES) {
            float4 o0 = make_float4(acc[i][0].f[0] + bias[0], acc[i][0].f[1] + bias[1],
                                    acc[i][1].f[0] + bias[2], acc[i][1].f[1] + bias[3]);
            float4 o1 = make_float4(acc[i][2].f[0] + bias[4], acc[i][2].f[1] + bias[5],
                                    acc[i][3].f[0] + bias[6], acc[i][3].f[1] + bias[7]);
            float4* dst = (float4*)&g_NP[(size_t)n * 256 + cx * 8];
            dst[0] = o0; dst[1] = o1;
        }
    }
}

// ---------------- kernel 2: fused edge GEMM + gather + activation + scatter ----------------
// 128 edges per block, 256 threads. Each thread: 4 edges x 8 cols, BOTH f and s
// halves (64 accumulator floats) -> activation straight from registers, no
// staging, no post-mainloop sync. Epilogue gathers node projections and
// scatter-adds with red.global.v4.
__global__ void __launch_bounds__(256, 2) edge_fused(
    const float* __restrict__ ea, const void* __restrict__ ei,
    const float* __restrict__ Wf, const float* __restrict__ Ws)
{
    __shared__ float Ast[32][132];   // A transposed: [k][edge], 128 edges
    __shared__ float Bs[32][128];    // [k][col]: cols 0-63 f, 64-127 s
    __shared__ int s_src[128], s_tgt[128];

    const int tid = threadIdx.x;
    const int eb = blockIdx.x * 128;

    if (tid < 128) {
        int src, tgt;
        if (g_is64) {
            src = (int)((const long long*)ei)[eb + tid];
            tgt = (int)((const long long*)ei)[N_EDGES + eb + tid];
        } else {
            src = ((const int*)ei)[eb + tid];
            tgt = ((const int*)ei)[N_EDGES + eb + tid];
        }
        s_src[tid] = src;
        s_tgt[tid] = tgt;
    }
    // A: edge_attrs tile transposed (128 x 32 -> [k][e])
#pragma unroll
    for (int it = 0; it < 16; ++it) {
        int idx = it * 256 + tid;
        int e = idx >> 5, k = idx & 31;
        Ast[k][e] = ea[(size_t)(eb + e) * 32 + k];
    }
    // B: rows 128..159 of W_f (cols 0..63) and W_s (cols 64..127)
#pragma unroll
    for (int it = 0; it < 16; ++it) {
        int idx = it * 256 + tid;
        int k = idx >> 7, c = idx & 127;
        Bs[k][c] = (c < 64) ? Wf[(128 + k) * 64 + c]
                            : Ws[(128 + k) * 64 + (c - 64)];
    }
    __syncthreads();

    const int cx = tid & 7;    // col group: cols 8*cx .. 8*cx+7 (both halves)
    const int ey = tid >> 3;   // edge group: edges 4*ey .. 4*ey+3 (of 128)

    F2U af[4][4], as_[4][4];
#pragma unroll
    for (int i = 0; i < 4; ++i)
#pragma unroll
        for (int j = 0; j < 4; ++j) { af[i][j].u = 0ULL; as_[i][j].u = 0ULL; }

#pragma unroll 8
    for (int k = 0; k < 32; ++k) {
        float4 av = *(const float4*)&Ast[k][ey * 4];
        float4 f0 = *(const float4*)&Bs[k][cx * 8];
        float4 f1 = *(const float4*)&Bs[k][cx * 8 + 4];
        float4 s0 = *(const float4*)&Bs[k][64 + cx * 8];
        float4 s1 = *(const float4*)&Bs[k][64 + cx * 8 + 4];
        unsigned long long bf_[4] = { pk2(f0.x, f0.y), pk2(f0.z, f0.w),
                                      pk2(f1.x, f1.y), pk2(f1.z, f1.w) };
        unsigned long long bs_[4] = { pk2(s0.x, s0.y), pk2(s0.z, s0.w),
                                      pk2(s1.x, s1.y), pk2(s1.z, s1.w) };
        float a[4] = { av.x, av.y, av.z, av.w };
#pragma unroll
        for (int i = 0; i < 4; ++i) {
            unsigned long long aa = pk2(a[i], a[i]);
#pragma unroll
            for (int j = 0; j < 4; ++j) {
                af[i][j].u  = ffma2(aa, bf_[j], af[i][j].u);
                as_[i][j].u = ffma2(aa, bs_[j], as_[i][j].u);
            }
        }
    }

    // epilogue straight from registers: gather NP, activate, scatter
    const int c4 = cx * 2;   // float4 index of col 8*cx within a 64-col section
#pragma unroll 2
    for (int i = 0; i < 4; ++i) {
        int e = ey * 4 + i;
        int src = s_src[e], tgt = s_tgt[e];
        const float4* np  = (const float4*)(g_NP + (size_t)src * 256);
        const float4* npT = (const float4*)(g_NP + (size_t)tgt * 256);
        float4 sf0 = np[c4],       sf1 = np[c4 + 1];        // src, f
        float4 ss0 = np[16 + c4],  ss1 = np[17 + c4];        // src, s
        float4 tf0 = npT[32 + c4], tf1 = npT[33 + c4];       // tgt, f
        float4 ts0 = npT[48 + c4], ts1 = npT[49 + c4];       // tgt, s

        float fv[8] = { af[i][0].f[0] + sf0.x + tf0.x, af[i][0].f[1] + sf0.y + tf0.y,
                        af[i][1].f[0] + sf0.z + tf0.z, af[i][1].f[1] + sf0.w + tf0.w,
                        af[i][2].f[0] + sf1.x + tf1.x, af[i][2].f[1] + sf1.y + tf1.y,
                        af[i][3].f[0] + sf1.z + tf1.z, af[i][3].f[1] + sf1.w + tf1.w };
        float sv[8] = { as_[i][0].f[0] + ss0.x + ts0.x, as_[i][0].f[1] + ss0.y + ts0.y,
                        as_[i][1].f[0] + ss0.z + ts0.z, as_[i][1].f[1] + ss0.w + ts0.w,
                        as_[i][2].f[0] + ss1.x + ts1.x, as_[i][2].f[1] + ss1.y + ts1.y,
                        as_[i][3].f[0] + ss1.z + ts1.z, as_[i][3].f[1] + ss1.w + ts1.w };
        float h[8];
#pragma unroll
        for (int j = 0; j < 8; ++j)
            h[j] = sigmoidf_(fv[j]) * softplusf_(sv[j]);

        float* dst = g_msg + (size_t)src * 64 + cx * 8;
        red4(dst,     h[0], h[1], h[2], h[3]);
        red4(dst + 4, h[4], h[5], h[6], h[7]);
    }
}

// ---------------- kernel 3: BN statistics reduction (float4, 2-level) ----------------
__global__ void __launch_bounds__(256) bn_reduce() {
    __shared__ float shs[16][68];
    __shared__ float sh2[16][68];
    const int tid = threadIdx.x;
    const int cg = tid & 15;    // col group of 4 (cols 4*cg .. 4*cg+3)
    const int ng = tid >> 4;    // node sub-group 0..15

    float4 s  = make_float4(0.f, 0.f, 0.f, 0.f);
    float4 s2 = make_float4(0.f, 0.f, 0.f, 0.f);
    for (int n = blockIdx.x * 16 + ng; n < N_NODES; n += gridDim.x * 16) {
        float4 v = *(const float4*)(g_msg + (size_t)n * 64 + cg * 4);
        s.x += v.x; s.y += v.y; s.z += v.z; s.w += v.w;
        s2.x += v.x * v.x; s2.y += v.y * v.y; s2.z += v.z * v.z; s2.w += v.w * v.w;
    }
    *(float4*)&shs[ng][cg * 4] = s;
    *(float4*)&sh2[ng][cg * 4] = s2;
    __syncthreads();
    if (tid < 64) {
        float a = 0.f, b = 0.f;
#pragma unroll
        for (int g = 0; g < 16; ++g) { a += shs[g][tid]; b += sh2[g][tid]; }
        atomicAdd(&g_stats[tid], (double)a);
        atomicAdd(&g_stats[64 + tid], (double)b);
    }
}

__global__ void bn_stats(const float* __restrict__ gamma, const float* __restrict__ beta) {
    int f = threadIdx.x;
    double invN = 1.0 / (double)N_NODES;
    double mean = g_stats[f] * invN;
    double var = g_stats[64 + f] * invN - mean * mean;
    if (var < 0.0) var = 0.0;
    float sc = (float)(rsqrt(var + 1e-5) * (double)gamma[f]);
    g_scale[f] = sc;
    g_shift[f] = beta[f] - (float)mean * sc;
}

// ---------------- kernel 4: residual + affine BN apply ----------------
__global__ void finalize(const float* __restrict__ node, float* __restrict__ out) {
    int idx = blockIdx.x * blockDim.x + threadIdx.x;     // float4 index, exact cover
    float4 m = ((const float4*)g_msg)[idx];
    float4 x = ((const float4*)node)[idx];
    int f0 = (idx * 4) & 63;
    float4 r;
    r.x = x.x + m.x * g_scale[f0]     + g_shift[f0];
    r.y = x.y + m.y * g_scale[f0 + 1] + g_shift[f0 + 1];
    r.z = x.z + m.z * g_scale[f0 + 2] + g_shift[f0 + 2];
    r.w = x.w + m.w * g_scale[f0 + 3] + g_shift[f0 + 3];
    ((float4*)out)[idx] = r;
}

// ---------------- launch ----------------
extern "C" void kernel_launch(void* const* d_in, const int* in_sizes, int n_in,
                              void* d_out, int out_size) {
    const float* node  = (const float*)d_in[0];
    const void*  ei    = d_in[1];
    const float* ea    = (const float*)d_in[2];
    const float* Wf    = (const float*)d_in[3];
    const float* bf    = (const float*)d_in[4];
    const float* Ws    = (const float*)d_in[5];
    const float* bs    = (const float*)d_in[6];
    const float* gamma = (const float*)d_in[7];
    const float* beta  = (const float*)d_in[8];
    float* out = (float*)d_out;

    void* pmsg = nullptr; void* pstats = nullptr;
    cudaGetSymbolAddress(&pmsg, g_msg);
    cudaGetSymbolAddress(&pstats, g_stats);
    cudaMemsetAsync(pmsg, 0, (size_t)N_NODES * 64 * sizeof(float));
    cudaMemsetAsync(pstats, 0, 128 * sizeof(double));

    detect_dtype<<<1, 256>>>((const unsigned int*)ei);
    node_gemm<<<(N_NODES + 63) / 64, 256>>>(node, Wf, bf, Ws, bs);
    edge_fused<<<N_EDGES / 128, 256>>>(ea, ei, Wf, Ws);
    bn_reduce<<<592, 256>>>();
    bn_stats<<<1, 64>>>(gamma, beta);
    finalize<<<(N_NODES * 64) / 1024, 256>>>(node, out);
}